// round 7
// baseline (speedup 1.0000x reference)
#include <cuda_runtime.h>

// RMAC max-pooling, x: (64, 37, 37, 512) f32 NHWC -> out: (64, 14, 512) f32.
// Regions = products of 6 x-intervals and 6 y-intervals:
//   0:[0,37) 1:[0,24) 2:[13,37) 3:[0,18) 4:[9,27) 5:[19,37)
//   r0:(y0,x0) r1:(y1,x1) r2:(y1,x2) r3:(y2,x1) r4:(y2,x2)
//   r5-7:(y3,x3/4/5) r8-10:(y4,x3/4/5) r11-13:(y5,x3/4/5)
//
// R7: single fused kernel. Grid (37, 64) = 2368 blocks = exactly 16 full
// waves on 148 SMs, each block 1 uniform row with 7 register accumulators
// (R2's proven 6.3 TB/s profile). Each block writes its row's 6 x-interval
// maxes to g_P, then the LAST block of each batch (threadfence + counter)
// performs the y-reduction straight from L2 (that batch's 454 KB was just
// written) and emits the 14 region outputs. Kills K2's launch + DRAM read.

#define NEG_INF __int_as_float(0xff800000)

// Per-row x-interval maxes: [64][6 x-int][37 rows][512 ch] = 29.1 MB.
__device__ float g_P[64 * 6 * 37 * 512];
// Per-batch arrival counters (zero-init; finisher resets -> replay-safe).
__device__ int g_cnt[64];

__device__ __forceinline__ float4 fmax4(float4 a, float4 b) {
    return make_float4(fmaxf(a.x, b.x), fmaxf(a.y, b.y),
                       fmaxf(a.z, b.z), fmaxf(a.w, b.w));
}

__global__ __launch_bounds__(128) void rmac_fused(const float* __restrict__ x,
                                                  float* __restrict__ out) {
    const int h  = blockIdx.x;   // row 0..36
    const int b  = blockIdx.y;   // batch 0..63
    const int c4 = threadIdx.x;  // float4 channel idx 0..127

    const float4* __restrict__ x4 = (const float4*)x;
    const float4 ninf = make_float4(NEG_INF, NEG_INF, NEG_INF, NEG_INF);

    float4 s0 = ninf, s1 = ninf, s2 = ninf, s3 = ninf,
           s4 = ninf, s5 = ninf, s6 = ninf;

    // Stream this row: 37 independent LDG.128, compile-time segment binning.
    size_t rb = ((size_t)(b * 37 + h) * 37) * 128 + c4;
#pragma unroll
    for (int w = 0; w < 37; ++w) {
        float4 v = x4[rb + (size_t)w * 128];
        if      (w <  9) s0 = fmax4(s0, v);
        else if (w < 13) s1 = fmax4(s1, v);
        else if (w < 18) s2 = fmax4(s2, v);
        else if (w < 19) s3 = fmax4(s3, v);
        else if (w < 24) s4 = fmax4(s4, v);
        else if (w < 27) s5 = fmax4(s5, v);
        else             s6 = fmax4(s6, v);
    }

    // 7 w-segments -> 6 x-interval maxes.
    float4 I3 = fmax4(fmax4(s0, s1), s2);                        // [0,18)
    float4 I1 = fmax4(fmax4(I3, s3), s4);                        // [0,24)
    float4 I5 = fmax4(fmax4(s4, s5), s6);                        // [19,37)
    float4 I0 = fmax4(I1, fmax4(s5, s6));                        // [0,37)
    float4 I2 = fmax4(fmax4(s2, s3), I5);                        // [13,37)
    float4 I4 = fmax4(fmax4(s1, s2), fmax4(s3, fmax4(s4, s5)));  // [9,27)

    // Table layout [b][i][h][512]: finisher reads are contiguous per i.
    float4* P4 = (float4*)g_P;
    size_t tb = ((size_t)(b * 6) * 37 + h) * 128 + c4;
    P4[tb + (size_t)(0 * 37) * 128] = I0;
    P4[tb + (size_t)(1 * 37) * 128] = I1;
    P4[tb + (size_t)(2 * 37) * 128] = I2;
    P4[tb + (size_t)(3 * 37) * 128] = I3;
    P4[tb + (size_t)(4 * 37) * 128] = I4;
    P4[tb + (size_t)(5 * 37) * 128] = I5;

    // Make this block's table writes visible, then count arrival.
    __threadfence();
    __syncthreads();
    __shared__ int isLast;
    if (threadIdx.x == 0) {
        int old = atomicAdd(&g_cnt[b], 1);
        isLast = (old == 36);
    }
    __syncthreads();
    if (!isLast) return;

    // ── Finisher: y-reduction for batch b straight from L2 ──
    const float4* __restrict__ Pr = (const float4*)g_P;
    float4* O4 = (float4*)out;
    const size_t ob = (size_t)b * 14 * 128 + c4;

    // x-int 0 -> r0 (y[0,37))
    {
        float4 a = ninf;
        size_t base = ((size_t)(b * 6 + 0) * 37) * 128 + c4;
#pragma unroll
        for (int hh = 0; hh < 37; ++hh) a = fmax4(a, Pr[base + (size_t)hh * 128]);
        O4[ob + 0 * 128] = a;
    }
    // x-int 1 -> r1 (y[0,24)), r3 (y[13,37));  x-int 2 -> r2, r4
#pragma unroll
    for (int i = 1; i <= 2; ++i) {
        float4 a1 = ninf, a2 = ninf;
        size_t base = ((size_t)(b * 6 + i) * 37) * 128 + c4;
#pragma unroll
        for (int hh = 0; hh < 37; ++hh) {
            float4 v = Pr[base + (size_t)hh * 128];
            if (hh < 24) a1 = fmax4(a1, v);
            if (hh >= 13) a2 = fmax4(a2, v);
        }
        O4[ob + (size_t)(i == 1 ? 1 : 2) * 128] = a1;
        O4[ob + (size_t)(i == 1 ? 3 : 4) * 128] = a2;
    }
    // x-int 3/4/5 -> (y3,y4,y5) = rows r5-7 / r8-10 / r11-13
#pragma unroll
    for (int i = 3; i <= 5; ++i) {
        float4 a3 = ninf, a4 = ninf, a5 = ninf;
        size_t base = ((size_t)(b * 6 + i) * 37) * 128 + c4;
#pragma unroll
        for (int hh = 0; hh < 37; ++hh) {
            float4 v = Pr[base + (size_t)hh * 128];
            if (hh < 18)             a3 = fmax4(a3, v);
            if (hh >= 9 && hh < 27)  a4 = fmax4(a4, v);
            if (hh >= 19)            a5 = fmax4(a5, v);
        }
        O4[ob + (size_t)(5  + (i - 3)) * 128] = a3;
        O4[ob + (size_t)(8  + (i - 3)) * 128] = a4;
        O4[ob + (size_t)(11 + (i - 3)) * 128] = a5;
    }

    // Reset counter for the next graph replay.
    if (threadIdx.x == 0) g_cnt[b] = 0;
}

extern "C" void kernel_launch(void* const* d_in, const int* in_sizes, int n_in,
                              void* d_out, int out_size) {
    const float* x = (const float*)d_in[0];
    float* out = (float*)d_out;

    rmac_fused<<<dim3(37, 64), 128>>>(x, out);
}

// round 8
// speedup vs baseline: 1.1605x; 1.1605x over previous
#include <cuda_runtime.h>

// RMAC max-pooling, x: (64, 37, 37, 512) f32 NHWC -> out: (64, 14, 512) f32.
// Regions = products of 6 x-intervals and 6 y-intervals:
//   0:[0,37) 1:[0,24) 2:[13,37) 3:[0,18) 4:[9,27) 5:[19,37)
//   r0:(y0,x0) r1:(y1,x1) r2:(y1,x2) r3:(y2,x1) r4:(y2,x2)
//   r5-7:(y3,x3/4/5) r8-10:(y4,x3/4/5) r11-13:(y5,x3/4/5)
//
// R8: no intermediate table. K1 (R6's proven streaming body: 17 sub-bands x
// 64 batches, 7 segment accumulators, float4 loads) folds its 6 x-interval
// maxes directly into a 1.8 MB u32 accumulator with atomicMax, using the
// monotone float<->u32 order-preserving map. max is idempotent => replay-
// deterministic, no resets. K2 is a trivial 1.8 MB u32->f32 transform
// (accumulator is atomic-hot in L2).

#define NEG_INF __int_as_float(0xff800000)
#define NSUB 17

// Output accumulator in order-preserving u32 space: [64][14][512] = 1.8 MB.
// Zero-init (module load) == -NaN sentinel, below every transformed value.
__device__ unsigned g_T[64 * 14 * 512];

__constant__ int c_sstart[NSUB] = {0, 2, 4, 7, 9, 11, 13, 15, 18, 19, 20, 22, 24, 27, 29, 32, 34};
__constant__ int c_slen[NSUB]   = {2, 2, 3, 2, 2, 2, 2, 3, 1, 1, 2, 2, 3, 2, 3, 2, 3};

__device__ __forceinline__ float4 fmax4(float4 a, float4 b) {
    return make_float4(fmaxf(a.x, b.x), fmaxf(a.y, b.y),
                       fmaxf(a.z, b.z), fmaxf(a.w, b.w));
}

// Monotone order-preserving map f32 -> u32 (and inverse).
__device__ __forceinline__ unsigned f2o(float f) {
    unsigned u = __float_as_uint(f);
    return (u & 0x80000000u) ? ~u : (u | 0x80000000u);
}
__device__ __forceinline__ float o2f(unsigned u) {
    unsigned b = (u & 0x80000000u) ? (u & 0x7FFFFFFFu) : ~u;
    return __uint_as_float(b);
}

__device__ __forceinline__ void amax4(unsigned* dst, float4 v) {
    atomicMax(dst + 0, f2o(v.x));
    atomicMax(dst + 1, f2o(v.y));
    atomicMax(dst + 2, f2o(v.z));
    atomicMax(dst + 3, f2o(v.w));
}

// K1: grid (17, 64) x 128 threads, float4 = full 512 channels per block.
__global__ __launch_bounds__(128) void rmac_k1(const float* __restrict__ x) {
    const int s  = blockIdx.x;   // sub-band 0..16
    const int b  = blockIdx.y;   // batch
    const int c4 = threadIdx.x;  // float4 channel idx 0..127

    const float4* __restrict__ x4 = (const float4*)x;

    const float4 ninf = make_float4(NEG_INF, NEG_INF, NEG_INF, NEG_INF);
    float4 s0 = ninf, s1 = ninf, s2 = ninf, s3 = ninf,
           s4 = ninf, s5 = ninf, s6 = ninf;

    const int h0  = c_sstart[s];
    const int len = c_slen[s];

    for (int hh = 0; hh < len; ++hh) {
        const int h = h0 + hh;
        size_t rb = ((size_t)(b * 37 + h) * 37) * 128 + c4;
#pragma unroll
        for (int w = 0; w < 37; ++w) {
            float4 v = x4[rb + (size_t)w * 128];
            if      (w <  9) s0 = fmax4(s0, v);
            else if (w < 13) s1 = fmax4(s1, v);
            else if (w < 18) s2 = fmax4(s2, v);
            else if (w < 19) s3 = fmax4(s3, v);
            else if (w < 24) s4 = fmax4(s4, v);
            else if (w < 27) s5 = fmax4(s5, v);
            else             s6 = fmax4(s6, v);
        }
    }

    // 7 w-segments -> 6 x-interval maxes.
    float4 I3 = fmax4(fmax4(s0, s1), s2);                        // [0,18)
    float4 I1 = fmax4(fmax4(I3, s3), s4);                        // [0,24)
    float4 I5 = fmax4(fmax4(s4, s5), s6);                        // [19,37)
    float4 I0 = fmax4(I1, fmax4(s5, s6));                        // [0,37)
    float4 I2 = fmax4(fmax4(s2, s3), I5);                        // [13,37)
    float4 I4 = fmax4(fmax4(s1, s2), fmax4(s3, fmax4(s4, s5)));  // [9,27)

    // Fold into the output accumulator for every region whose y-interval
    // contains this sub-band. Scalar slot: g_T[b][r][ch], ch = c4*4.
    unsigned* T = g_T + ((size_t)b * 14) * 512 + c4 * 4;

    const bool y1 = (s <= 11);            // rows < 24
    const bool y2 = (s >= 6);             // rows >= 13
    const bool y3 = (s <= 7);             // rows < 18
    const bool y4 = (s >= 4 && s <= 12);  // rows in [9,27)
    const bool y5 = (s >= 9);             // rows >= 19

    amax4(T + 0 * 512, I0);
    if (y1) { amax4(T +  1 * 512, I1); amax4(T +  2 * 512, I2); }
    if (y2) { amax4(T +  3 * 512, I1); amax4(T +  4 * 512, I2); }
    if (y3) { amax4(T +  5 * 512, I3); amax4(T +  6 * 512, I4); amax4(T +  7 * 512, I5); }
    if (y4) { amax4(T +  8 * 512, I3); amax4(T +  9 * 512, I4); amax4(T + 10 * 512, I5); }
    if (y5) { amax4(T + 11 * 512, I3); amax4(T + 12 * 512, I4); amax4(T + 13 * 512, I5); }
}

// K2: u32 -> f32 transform of the 1.8 MB accumulator (L2-hot).
// 64*14*512 = 458752 floats = 114688 uint4 -> 896 blocks x 128 threads.
__global__ __launch_bounds__(128) void rmac_k2(float* __restrict__ out) {
    const size_t i = (size_t)blockIdx.x * 128 + threadIdx.x;
    uint4 t = ((const uint4*)g_T)[i];
    ((float4*)out)[i] = make_float4(o2f(t.x), o2f(t.y), o2f(t.z), o2f(t.w));
}

extern "C" void kernel_launch(void* const* d_in, const int* in_sizes, int n_in,
                              void* d_out, int out_size) {
    const float* x = (const float*)d_in[0];
    float* out = (float*)d_out;

    rmac_k1<<<dim3(NSUB, 64), 128>>>(x);
    rmac_k2<<<896, 128>>>(out);
}

// round 9
// speedup vs baseline: 1.1982x; 1.0325x over previous
#include <cuda_runtime.h>

// RMAC max-pooling, x: (64, 37, 37, 512) f32 NHWC -> out: (64, 14, 512) f32.
// Regions = products of 6 x-intervals and 6 y-intervals:
//   0:[0,37) 1:[0,24) 2:[13,37) 3:[0,18) 4:[9,27) 5:[19,37)
//   r0:(y0,x0) r1:(y1,x1) r2:(y1,x2) r3:(y2,x1) r4:(y2,x2)
//   r5-7:(y3,x3/4/5) r8-10:(y4,x3/4/5) r11-13:(y5,x3/4/5)
//
// R9: K1 is byte-identical to R6 (proven 33.9us: 17 sub-band blocks, 7
// segment accs, float4). K2 redesigned as a flat gather: one thread per
// output element (64x14x128 float4s = 896x128 blocks); each thread does its
// region's 8-17 INDEPENDENT coalesced float4 loads from the contiguous
// [b][i][s] table row, a single fmax chain, one store. (R8 showed direct
// atomicMax costs +6us in K1; R6's K2 lost ~3us to serial shape/low occ.)

#define NEG_INF __int_as_float(0xff800000)
#define NSUB 17

// Partial table: [64][6 x-intervals][17 sub-bands][512 ch] = 13.4 MB.
__device__ float g_P[64 * 6 * NSUB * 512];

__constant__ int c_sstart[NSUB] = {0, 2, 4, 7, 9, 11, 13, 15, 18, 19, 20, 22, 24, 27, 29, 32, 34};
__constant__ int c_slen[NSUB]   = {2, 2, 3, 2, 2, 2, 2, 3, 1, 1, 2, 2, 3, 2, 3, 2, 3};

// Region -> x-interval and sub-band range [rs0, rs1).
__constant__ int c_rX[14]  = {0, 1, 2, 1, 2, 3, 4, 5, 3, 4, 5, 3, 4, 5};
__constant__ int c_rs0[14] = {0, 0, 0, 6, 6, 0, 0, 0, 4, 4, 4, 9, 9, 9};
__constant__ int c_rs1[14] = {17, 12, 12, 17, 17, 8, 8, 8, 13, 13, 13, 17, 17, 17};

__device__ __forceinline__ float4 fmax4(float4 a, float4 b) {
    return make_float4(fmaxf(a.x, b.x), fmaxf(a.y, b.y),
                       fmaxf(a.z, b.z), fmaxf(a.w, b.w));
}

// K1: grid (17, 64) x 128 threads, float4 = full 512 channels per block.
__global__ __launch_bounds__(128) void rmac_k1(const float* __restrict__ x) {
    const int s  = blockIdx.x;   // sub-band 0..16
    const int b  = blockIdx.y;   // batch
    const int c4 = threadIdx.x;  // float4 channel idx 0..127

    const float4* __restrict__ x4 = (const float4*)x;

    const float4 ninf = make_float4(NEG_INF, NEG_INF, NEG_INF, NEG_INF);
    float4 s0 = ninf, s1 = ninf, s2 = ninf, s3 = ninf,
           s4 = ninf, s5 = ninf, s6 = ninf;

    const int h0  = c_sstart[s];
    const int len = c_slen[s];

    for (int hh = 0; hh < len; ++hh) {
        const int h = h0 + hh;
        size_t rb = ((size_t)(b * 37 + h) * 37) * 128 + c4;
#pragma unroll
        for (int w = 0; w < 37; ++w) {
            float4 v = x4[rb + (size_t)w * 128];
            if      (w <  9) s0 = fmax4(s0, v);
            else if (w < 13) s1 = fmax4(s1, v);
            else if (w < 18) s2 = fmax4(s2, v);
            else if (w < 19) s3 = fmax4(s3, v);
            else if (w < 24) s4 = fmax4(s4, v);
            else if (w < 27) s5 = fmax4(s5, v);
            else             s6 = fmax4(s6, v);
        }
    }

    // 7 w-segments -> 6 x-interval maxes.
    float4 I3 = fmax4(fmax4(s0, s1), s2);                        // [0,18)
    float4 I1 = fmax4(fmax4(I3, s3), s4);                        // [0,24)
    float4 I5 = fmax4(fmax4(s4, s5), s6);                        // [19,37)
    float4 I0 = fmax4(I1, fmax4(s5, s6));                        // [0,37)
    float4 I2 = fmax4(fmax4(s2, s3), I5);                        // [13,37)
    float4 I4 = fmax4(fmax4(s1, s2), fmax4(s3, fmax4(s4, s5)));  // [9,27)

    // Table layout [b][i][s][512]: K2's per-(b,i) reads are contiguous in s.
    float4* P4 = (float4*)g_P;
    size_t base = ((size_t)(b * 6) * NSUB + s) * 128 + c4;
    P4[base + (size_t)(0 * NSUB) * 128] = I0;
    P4[base + (size_t)(1 * NSUB) * 128] = I1;
    P4[base + (size_t)(2 * NSUB) * 128] = I2;
    P4[base + (size_t)(3 * NSUB) * 128] = I3;
    P4[base + (size_t)(4 * NSUB) * 128] = I4;
    P4[base + (size_t)(5 * NSUB) * 128] = I5;
}

// K2: flat gather. grid (14, 64) x 128 threads; thread = one output float4.
// Each thread: 8-17 independent coalesced float4 loads, fmax chain, 1 store.
__global__ __launch_bounds__(128) void rmac_k2(float* __restrict__ out) {
    const int r  = blockIdx.x;   // region 0..13
    const int b  = blockIdx.y;   // batch
    const int c4 = threadIdx.x;  // float4 ch idx 0..127

    const int i  = c_rX[r];
    const int s0 = c_rs0[r];
    const int s1 = c_rs1[r];

    const float4* __restrict__ P4 = (const float4*)g_P;
    size_t base = ((size_t)(b * 6 + i) * NSUB) * 128 + c4;

    float4 a = make_float4(NEG_INF, NEG_INF, NEG_INF, NEG_INF);
#pragma unroll 17
    for (int s = s0; s < s1; ++s) {
        a = fmax4(a, P4[base + (size_t)s * 128]);
    }

    ((float4*)out)[((size_t)(b * 14 + r)) * 128 + c4] = a;
}

extern "C" void kernel_launch(void* const* d_in, const int* in_sizes, int n_in,
                              void* d_out, int out_size) {
    const float* x = (const float*)d_in[0];
    float* out = (float*)d_out;

    rmac_k1<<<dim3(NSUB, 64), 128>>>(x);
    rmac_k2<<<dim3(14, 64), 128>>>(out);
}

// round 11
// speedup vs baseline: 1.2656x; 1.0563x over previous
#include <cuda_runtime.h>

// RMAC max-pooling, x: (64, 37, 37, 512) f32 NHWC -> out: (64, 14, 512) f32.
// Regions = products of 6 x-intervals and 6 y-intervals:
//   0:[0,37) 1:[0,24) 2:[13,37) 3:[0,18) 4:[9,27) 5:[19,37)
//   r0:(y0,x0) r1:(y1,x1) r2:(y1,x2) r3:(y2,x1) r4:(y2,x2)
//   r5-7:(y3,x3/4/5) r8-10:(y4,x3/4/5) r11-13:(y5,x3/4/5)
//
// R11 = R10 resubmit (R10 bench died with the same infra signature as R4,
// which passed on identical resubmit). Bodies byte-identical to R6; single
// variable vs R6 is Programmatic Dependent Launch: K1 CTAs trigger
// launch_dependents after their table stores, K2 waits via
// griddepcontrol.wait, so K2's ~4.5us launch/setup overlaps K1's drain.

#define NEG_INF __int_as_float(0xff800000)
#define NSUB 17

#define PDL_TRIGGER() asm volatile("griddepcontrol.launch_dependents;" ::: "memory")
#define PDL_WAIT()    asm volatile("griddepcontrol.wait;" ::: "memory")

// Partial table: [64][6 x-intervals][17 sub-bands][512 ch] = 13.4 MB.
__device__ float g_P[64 * 6 * NSUB * 512];

__constant__ int c_sstart[NSUB] = {0, 2, 4, 7, 9, 11, 13, 15, 18, 19, 20, 22, 24, 27, 29, 32, 34};
__constant__ int c_slen[NSUB]   = {2, 2, 3, 2, 2, 2, 2, 3, 1, 1, 2, 2, 3, 2, 3, 2, 3};

__device__ __forceinline__ float4 fmax4(float4 a, float4 b) {
    return make_float4(fmaxf(a.x, b.x), fmaxf(a.y, b.y),
                       fmaxf(a.z, b.z), fmaxf(a.w, b.w));
}

// K1: grid (17, 64) x 128 threads, float4 = full 512 channels per block.
__global__ __launch_bounds__(128) void rmac_k1(const float* __restrict__ x) {
    const int s  = blockIdx.x;   // sub-band 0..16
    const int b  = blockIdx.y;   // batch
    const int c4 = threadIdx.x;  // float4 channel idx 0..127

    const float4* __restrict__ x4 = (const float4*)x;

    const float4 ninf = make_float4(NEG_INF, NEG_INF, NEG_INF, NEG_INF);
    float4 s0 = ninf, s1 = ninf, s2 = ninf, s3 = ninf,
           s4 = ninf, s5 = ninf, s6 = ninf;

    const int h0  = c_sstart[s];
    const int len = c_slen[s];

    for (int hh = 0; hh < len; ++hh) {
        const int h = h0 + hh;
        size_t rb = ((size_t)(b * 37 + h) * 37) * 128 + c4;
#pragma unroll
        for (int w = 0; w < 37; ++w) {
            float4 v = x4[rb + (size_t)w * 128];
            if      (w <  9) s0 = fmax4(s0, v);
            else if (w < 13) s1 = fmax4(s1, v);
            else if (w < 18) s2 = fmax4(s2, v);
            else if (w < 19) s3 = fmax4(s3, v);
            else if (w < 24) s4 = fmax4(s4, v);
            else if (w < 27) s5 = fmax4(s5, v);
            else             s6 = fmax4(s6, v);
        }
    }

    // 7 w-segments -> 6 x-interval maxes.
    float4 I3 = fmax4(fmax4(s0, s1), s2);                        // [0,18)
    float4 I1 = fmax4(fmax4(I3, s3), s4);                        // [0,24)
    float4 I5 = fmax4(fmax4(s4, s5), s6);                        // [19,37)
    float4 I0 = fmax4(I1, fmax4(s5, s6));                        // [0,37)
    float4 I2 = fmax4(fmax4(s2, s3), I5);                        // [13,37)
    float4 I4 = fmax4(fmax4(s1, s2), fmax4(s3, fmax4(s4, s5)));  // [9,27)

    // Table layout [b][i][s][512]: K2's per-(b,i) reads are contiguous in s.
    float4* P4 = (float4*)g_P;
    size_t base = ((size_t)(b * 6) * NSUB + s) * 128 + c4;
    P4[base + (size_t)(0 * NSUB) * 128] = I0;
    P4[base + (size_t)(1 * NSUB) * 128] = I1;
    P4[base + (size_t)(2 * NSUB) * 128] = I2;
    P4[base + (size_t)(3 * NSUB) * 128] = I3;
    P4[base + (size_t)(4 * NSUB) * 128] = I4;
    P4[base + (size_t)(5 * NSUB) * 128] = I5;

    // PDL: this CTA's table writes are now visible to the dependent grid.
    PDL_TRIGGER();
}

// Sub-band s -> bitmask of y-intervals containing it (bit y set).
// y0 all; y1 s<=11; y2 s>=6; y3 s<=7; y4 4<=s<=12; y5 s>=9.
#define YMASK(s) ((unsigned)(1u \
    | ((s) <= 11 ? 2u : 0u) \
    | ((s) >=  6 ? 4u : 0u) \
    | ((s) <=  7 ? 8u : 0u) \
    | (((s) >= 4 && (s) <= 12) ? 16u : 0u) \
    | ((s) >=  9 ? 32u : 0u)))

// K2: grid (6, 64, 2) x 64 threads, float4 (256 ch per block).
__global__ __launch_bounds__(64) void rmac_k2(float* __restrict__ out) {
    const int i  = blockIdx.x;                      // x-interval 0..5
    const int b  = blockIdx.y;
    const int c4 = blockIdx.z * 64 + threadIdx.x;   // float4 ch idx 0..127

    const float4 ninf = make_float4(NEG_INF, NEG_INF, NEG_INF, NEG_INF);
    float4 Y[6];
#pragma unroll
    for (int y = 0; y < 6; ++y) Y[y] = ninf;

    size_t base = ((size_t)(b * 6 + i) * NSUB) * 128 + c4;

    // Wait for all K1 CTAs' triggers (table fully written & visible).
    PDL_WAIT();

    const float4* __restrict__ P4 = (const float4*)g_P;
#pragma unroll
    for (int s = 0; s < NSUB; ++s) {
        float4 v = P4[base + (size_t)s * 128];
        const unsigned m = YMASK(s);
        if (m & 1u)  Y[0] = fmax4(Y[0], v);
        if (m & 2u)  Y[1] = fmax4(Y[1], v);
        if (m & 4u)  Y[2] = fmax4(Y[2], v);
        if (m & 8u)  Y[3] = fmax4(Y[3], v);
        if (m & 16u) Y[4] = fmax4(Y[4], v);
        if (m & 32u) Y[5] = fmax4(Y[5], v);
    }

    float4* O4 = (float4*)out;
    size_t ob = (size_t)b * 14 * 128 + c4;
    switch (i) {
        case 0: O4[ob +  0 * 128] = Y[0]; break;
        case 1: O4[ob +  1 * 128] = Y[1]; O4[ob +  3 * 128] = Y[2]; break;
        case 2: O4[ob +  2 * 128] = Y[1]; O4[ob +  4 * 128] = Y[2]; break;
        case 3: O4[ob +  5 * 128] = Y[3]; O4[ob +  8 * 128] = Y[4];
                O4[ob + 11 * 128] = Y[5]; break;
        case 4: O4[ob +  6 * 128] = Y[3]; O4[ob +  9 * 128] = Y[4];
                O4[ob + 12 * 128] = Y[5]; break;
        case 5: O4[ob +  7 * 128] = Y[3]; O4[ob + 10 * 128] = Y[4];
                O4[ob + 13 * 128] = Y[5]; break;
    }
}

extern "C" void kernel_launch(void* const* d_in, const int* in_sizes, int n_in,
                              void* d_out, int out_size) {
    const float* x = (const float*)d_in[0];
    float* out = (float*)d_out;

    rmac_k1<<<dim3(NSUB, 64), 128>>>(x);

    // K2 with Programmatic Dependent Launch: overlap its launch/setup with
    // K1's drain; correctness ordered by griddepcontrol.wait in-kernel.
    cudaLaunchConfig_t cfg = {};
    cfg.gridDim = dim3(6, 64, 2);
    cfg.blockDim = dim3(64, 1, 1);
    cfg.dynamicSmemBytes = 0;
    cfg.stream = 0;
    cudaLaunchAttribute attr[1];
    attr[0].id = cudaLaunchAttributeProgrammaticStreamSerialization;
    attr[0].val.programmaticStreamSerializationAllowed = 1;
    cfg.attrs = attr;
    cfg.numAttrs = 1;
    cudaLaunchKernelEx(&cfg, rmac_k2, out);
}